// round 1
// baseline (speedup 1.0000x reference)
#include <cuda_runtime.h>
#include <math.h>

#define NUM_CLASSES 16
#define MARGIN 0.3f
#define EPS 1e-8f

// ---------------- device-global scratch (no allocations allowed) ----------------
__device__ int   g_first_idx[NUM_CLASSES];
__device__ int   g_present[NUM_CLASSES];
__device__ int   g_ua64;          // 1 if user_answers is int64, 0 if int32
__device__ float g_D[NUM_CLASSES * NUM_CLASSES];
__device__ float g_S[NUM_CLASSES * NUM_CLASSES];
__device__ float g_sum_rank;
__device__ float g_sum_per;
__device__ int   g_cnt;
__device__ unsigned g_done;

// ---------------- K1: dtype detection + first_idx + accumulator reset ----------------
// Single block. targets_mat has n_tm elements; user_answers has n_ua_elems elements.
__global__ void k1_prep(const void* __restrict__ tm, const void* __restrict__ ua,
                        int n_tm, int n_ua_elems) {
    __shared__ int s_first[NUM_CLASSES];
    __shared__ int s_tm_nz, s_ua_nz;
    int tid = threadIdx.x;

    if (tid == 0) { s_tm_nz = 0; s_ua_nz = 0; }
    if (tid < NUM_CLASSES) s_first[tid] = 0x7fffffff;
    __syncthreads();

    // dtype detection: if arrays are int64, every odd 32-bit word is 0 (values in [0,16)).
    // If int32, odd-index elements are random in [0,16) -> some nonzero with prob ~1.
    const unsigned* tw = (const unsigned*)tm;
    const unsigned* uw = (const unsigned*)ua;
    for (int i = tid; i < 1024; i += blockDim.x) {
        int wi = 2 * i + 1;
        if (wi < n_tm && tw[wi] != 0u) s_tm_nz = 1;          // n_tm words is the minimum size
        if (wi < n_ua_elems && uw[wi] != 0u) s_ua_nz = 1;
    }
    __syncthreads();
    int tm64 = (s_tm_nz == 0);

    // first occurrence of each class in targets_mat
    for (int i = tid; i < n_tm; i += blockDim.x) {
        int c;
        if (tm64) c = (int)((const long long*)tm)[i];
        else      c = ((const int*)tm)[i];
        if ((unsigned)c < (unsigned)NUM_CLASSES) atomicMin(&s_first[c], i);
    }
    __syncthreads();

    if (tid < NUM_CLASSES) {
        int f = s_first[tid];
        g_present[tid]   = (f != 0x7fffffff) ? 1 : 0;
        g_first_idx[tid] = (f == 0x7fffffff) ? 0 : f;   // argmax of all-false row == 0
    }
    if (tid == 0) {
        g_ua64 = (s_ua_nz == 0) ? 1 : 0;
        g_sum_rank = 0.0f;
        g_sum_per  = 0.0f;
        g_cnt  = 0;
        g_done = 0u;
    }
}

// ---------------- K2: 16x16 distance table ----------------
// Grid 256 blocks (one per (i,j) pair), 128 threads each.
__global__ void k2_dist(const float* __restrict__ inputs, int D) {
    int i = blockIdx.x >> 4;
    int j = blockIdx.x & 15;
    int fi = g_first_idx[i];
    int fj = g_first_idx[j];
    const float4* a = (const float4*)(inputs + (size_t)fi * D);
    const float4* b = (const float4*)(inputs + (size_t)fj * D);
    int nvec = D >> 2;

    float s = 0.0f;
    for (int k = threadIdx.x; k < nvec; k += blockDim.x) {
        float4 x = __ldg(a + k);
        float4 y = __ldg(b + k);
        float d0 = x.x - y.x, d1 = x.y - y.y, d2 = x.z - y.z, d3 = x.w - y.w;
        s = fmaf(d0, d0, s); s = fmaf(d1, d1, s);
        s = fmaf(d2, d2, s); s = fmaf(d3, d3, s);
    }
    #pragma unroll
    for (int o = 16; o > 0; o >>= 1) s += __shfl_xor_sync(0xffffffffu, s, o);

    __shared__ float sp[4];
    if ((threadIdx.x & 31) == 0) sp[threadIdx.x >> 5] = s;
    __syncthreads();
    if (threadIdx.x == 0) {
        float d2sum = sp[0] + sp[1] + sp[2] + sp[3];
        d2sum = fmaxf(d2sum, 1e-12f);
        float d = sqrtf(d2sum);
        g_D[blockIdx.x] = d;
        g_S[blockIdx.x] = 1.0f / (d + 1.0f);
    }
}

// ---------------- K3: main reduction over T triples + finalize ----------------
__global__ void k3_main(const void* __restrict__ ua, int T, int nblocks,
                        float* __restrict__ out) {
    int t = blockIdx.x * blockDim.x + threadIdx.x;
    float rk = 0.0f, pr = 0.0f;
    int v = 0;

    if (t < T) {
        int c0, c1, c2;
        if (g_ua64) {
            const long long* p = (const long long*)ua + (size_t)3 * t;
            c0 = (int)p[0]; c1 = (int)p[1]; c2 = (int)p[2];
        } else {
            const int* p = (const int*)ua + (size_t)3 * t;
            c0 = p[0]; c1 = p[1]; c2 = p[2];
        }
        bool inrange = ((unsigned)c0 < 16u) & ((unsigned)c1 < 16u) & ((unsigned)c2 < 16u);
        if (inrange && g_present[c0] && g_present[c1] && g_present[c2]) {
            v = 1;
            int iap = c0 * 16 + c1;
            int ian = c0 * 16 + c2;
            float dap = __ldg(&g_D[iap]);
            float dan = __ldg(&g_D[ian]);
            rk = fmaxf(dap - dan + MARGIN, 0.0f);
            float sap = __ldg(&g_S[iap]);
            float san = __ldg(&g_S[ian]);
            pr = -logf(sap / (sap + san) + EPS);
        }
    }

    #pragma unroll
    for (int o = 16; o > 0; o >>= 1) {
        rk += __shfl_xor_sync(0xffffffffu, rk, o);
        pr += __shfl_xor_sync(0xffffffffu, pr, o);
        v  += __shfl_xor_sync(0xffffffffu, v,  o);
    }

    __shared__ float srk[8], spr[8];
    __shared__ int   sv[8];
    int w = threadIdx.x >> 5;
    if ((threadIdx.x & 31) == 0) { srk[w] = rk; spr[w] = pr; sv[w] = v; }
    __syncthreads();

    if (threadIdx.x == 0) {
        float R = 0.0f, P = 0.0f; int V = 0;
        int nw = blockDim.x >> 5;
        for (int k = 0; k < nw; k++) { R += srk[k]; P += spr[k]; V += sv[k]; }
        atomicAdd(&g_sum_rank, R);
        atomicAdd(&g_sum_per,  P);
        atomicAdd(&g_cnt,      V);
        __threadfence();
        unsigned d = atomicAdd(&g_done, 1u);
        if (d == (unsigned)(nblocks - 1)) {
            float sr = atomicAdd(&g_sum_rank, 0.0f);
            float sp2 = atomicAdd(&g_sum_per, 0.0f);
            int   cn = atomicAdd(&g_cnt, 0);
            float nv = fmaxf((float)cn, 1.0f);
            float lh = sr / nv;
            float lp = sp2 / nv;
            out[0] = lh + lp;
            out[1] = lh;
            out[2] = lp;
        }
    }
}

// ---------------- launch ----------------
// Inputs (metadata order): 0 preds_mat(f32), 1 preds_sub(f32), 2 inputs(f32 B*D),
// 3 targets_mat(int, B), 4 targets_sub(int, B), 5 user_answers(int, T*3)
extern "C" void kernel_launch(void* const* d_in, const int* in_sizes, int n_in,
                              void* d_out, int out_size) {
    const float* inputs = (const float*)d_in[2];
    const void*  tm     = d_in[3];
    const void*  ua     = d_in[5];
    int n_tm = in_sizes[3];
    int n_ua = in_sizes[5];
    int T = n_ua / 3;
    int D = in_sizes[2] / n_tm;

    k1_prep<<<1, 256>>>(tm, ua, n_tm, n_ua);
    k2_dist<<<NUM_CLASSES * NUM_CLASSES, 128>>>(inputs, D);
    int nb = (T + 255) / 256;
    k3_main<<<nb, 256>>>(ua, T, nb, (float*)d_out);
}

// round 2
// speedup vs baseline: 1.6078x; 1.6078x over previous
#include <cuda_runtime.h>
#include <math.h>

#define NUM_CLASSES 16
#define MARGIN 0.3f
#define EPS 1e-8f

// ---------------- device-global scratch (no allocations allowed) ----------------
__device__ int   g_first_idx[NUM_CLASSES];
__device__ int   g_present[NUM_CLASSES];
__device__ int   g_ua64;          // 1 if user_answers is int64, 0 if int32
__device__ float g_D[NUM_CLASSES * NUM_CLASSES];
__device__ float g_S[NUM_CLASSES * NUM_CLASSES];
__device__ float g_sum_rank;
__device__ float g_sum_per;
__device__ int   g_cnt;
__device__ unsigned g_done;

// ---------------- K1: dtype detection + first_idx + accumulator reset ----------------
// Single block, 1024 threads. Structured in 3 phases so that each phase's DRAM
// loads are front-batched (MLP >= 4) instead of one exposed latency per loop
// iteration.
__global__ __launch_bounds__(1024) void k1_prep(const void* __restrict__ tm,
                                                const void* __restrict__ ua,
                                                int n_tm, int n_ua_elems) {
    __shared__ int s_first[NUM_CLASSES];
    __shared__ int s_tm64, s_ua64;
    int tid = threadIdx.x;
    int nthr = blockDim.x;

    if (tid < NUM_CLASSES) s_first[tid] = 0x7fffffff;
    if (tid == 0) { s_tm64 = 1; s_ua64 = 1; }
    __syncthreads();

    const unsigned* tw = (const unsigned*)tm;
    const unsigned* uw = (const unsigned*)ua;

    // ---- Phase A: dtype detection. Values are in [0,16), so if the arrays are
    // int64 every odd 32-bit word is 0; if int32, odd-index ELEMENTS are random
    // in [0,16) and some are nonzero with overwhelming probability.
    // Sample up to 8192 words (safe: min array size is n_tm / n_ua_elems words).
    {
        int lim_t = n_tm < 8192 ? n_tm : 8192;
        int lim_u = n_ua_elems < 8192 ? n_ua_elems : 8192;
        unsigned vt = 0u, vu = 0u;
        unsigned a0=0,a1=0,a2=0,a3=0,b0=0,b1=0,b2=0,b3=0;
        int w0 = 2*tid+1;
        int s  = 2*nthr;
        if (w0         < lim_t) a0 = tw[w0];
        if (w0 +   s   < lim_t) a1 = tw[w0+s];
        if (w0 + 2*s   < lim_t) a2 = tw[w0+2*s];
        if (w0 + 3*s   < lim_t) a3 = tw[w0+3*s];
        if (w0         < lim_u) b0 = uw[w0];
        if (w0 +   s   < lim_u) b1 = uw[w0+s];
        if (w0 + 2*s   < lim_u) b2 = uw[w0+2*s];
        if (w0 + 3*s   < lim_u) b3 = uw[w0+3*s];
        vt = a0|a1|a2|a3;
        vu = b0|b1|b2|b3;
        if (vt) s_tm64 = 0;
        if (vu) s_ua64 = 0;
    }
    __syncthreads();
    int tm64 = s_tm64;

    // ---- Phase B+C: first occurrence of each class in targets_mat.
    // Front-batch 4 independent loads per thread per outer iteration, then do
    // the shared atomics on register-resident values.
    for (int base = 0; base < n_tm; base += 4*nthr) {
        unsigned w0 = 0xffffffffu, w1 = 0xffffffffu, w2 = 0xffffffffu, w3 = 0xffffffffu;
        int i0 = base + tid;
        int i1 = i0 + nthr;
        int i2 = i1 + nthr;
        int i3 = i2 + nthr;
        if (tm64) {
            if (i0 < n_tm) w0 = tw[2*i0];
            if (i1 < n_tm) w1 = tw[2*i1];
            if (i2 < n_tm) w2 = tw[2*i2];
            if (i3 < n_tm) w3 = tw[2*i3];
        } else {
            if (i0 < n_tm) w0 = tw[i0];
            if (i1 < n_tm) w1 = tw[i1];
            if (i2 < n_tm) w2 = tw[i2];
            if (i3 < n_tm) w3 = tw[i3];
        }
        if (w0 < (unsigned)NUM_CLASSES) atomicMin(&s_first[w0], i0);
        if (w1 < (unsigned)NUM_CLASSES) atomicMin(&s_first[w1], i1);
        if (w2 < (unsigned)NUM_CLASSES) atomicMin(&s_first[w2], i2);
        if (w3 < (unsigned)NUM_CLASSES) atomicMin(&s_first[w3], i3);
    }
    __syncthreads();

    if (tid < NUM_CLASSES) {
        int f = s_first[tid];
        g_present[tid]   = (f != 0x7fffffff) ? 1 : 0;
        g_first_idx[tid] = (f == 0x7fffffff) ? 0 : f;   // argmax of all-false row == 0
    }
    if (tid == 0) {
        g_ua64 = s_ua64;
        g_sum_rank = 0.0f;
        g_sum_per  = 0.0f;
        g_cnt  = 0;
        g_done = 0u;
    }
}

// ---------------- K2: 16x16 distance table ----------------
// Grid 256 blocks (one per (i,j) pair), 128 threads each.
__global__ void k2_dist(const float* __restrict__ inputs, int D) {
    int i = blockIdx.x >> 4;
    int j = blockIdx.x & 15;
    int fi = g_first_idx[i];
    int fj = g_first_idx[j];
    const float4* a = (const float4*)(inputs + (size_t)fi * D);
    const float4* b = (const float4*)(inputs + (size_t)fj * D);
    int nvec = D >> 2;

    float s = 0.0f;
    for (int k = threadIdx.x; k < nvec; k += blockDim.x) {
        float4 x = __ldg(a + k);
        float4 y = __ldg(b + k);
        float d0 = x.x - y.x, d1 = x.y - y.y, d2 = x.z - y.z, d3 = x.w - y.w;
        s = fmaf(d0, d0, s); s = fmaf(d1, d1, s);
        s = fmaf(d2, d2, s); s = fmaf(d3, d3, s);
    }
    #pragma unroll
    for (int o = 16; o > 0; o >>= 1) s += __shfl_xor_sync(0xffffffffu, s, o);

    __shared__ float sp[4];
    if ((threadIdx.x & 31) == 0) sp[threadIdx.x >> 5] = s;
    __syncthreads();
    if (threadIdx.x == 0) {
        float d2sum = sp[0] + sp[1] + sp[2] + sp[3];
        d2sum = fmaxf(d2sum, 1e-12f);
        float d = sqrtf(d2sum);
        g_D[blockIdx.x] = d;
        g_S[blockIdx.x] = 1.0f / (d + 1.0f);
    }
}

// ---------------- K3: main reduction over T triples + finalize ----------------
__global__ void k3_main(const void* __restrict__ ua, int T, int nblocks,
                        float* __restrict__ out) {
    int t = blockIdx.x * blockDim.x + threadIdx.x;
    float rk = 0.0f, pr = 0.0f;
    int v = 0;

    if (t < T) {
        int c0, c1, c2;
        if (g_ua64) {
            const long long* p = (const long long*)ua + (size_t)3 * t;
            c0 = (int)__ldg(p); c1 = (int)__ldg(p+1); c2 = (int)__ldg(p+2);
        } else {
            const int* p = (const int*)ua + (size_t)3 * t;
            c0 = __ldg(p); c1 = __ldg(p+1); c2 = __ldg(p+2);
        }
        bool inrange = ((unsigned)c0 < 16u) & ((unsigned)c1 < 16u) & ((unsigned)c2 < 16u);
        if (inrange && g_present[c0] && g_present[c1] && g_present[c2]) {
            v = 1;
            int iap = c0 * 16 + c1;
            int ian = c0 * 16 + c2;
            float dap = __ldg(&g_D[iap]);
            float dan = __ldg(&g_D[ian]);
            rk = fmaxf(dap - dan + MARGIN, 0.0f);
            float sap = __ldg(&g_S[iap]);
            float san = __ldg(&g_S[ian]);
            pr = -logf(sap / (sap + san) + EPS);
        }
    }

    #pragma unroll
    for (int o = 16; o > 0; o >>= 1) {
        rk += __shfl_xor_sync(0xffffffffu, rk, o);
        pr += __shfl_xor_sync(0xffffffffu, pr, o);
        v  += __shfl_xor_sync(0xffffffffu, v,  o);
    }

    __shared__ float srk[8], spr[8];
    __shared__ int   sv[8];
    int w = threadIdx.x >> 5;
    if ((threadIdx.x & 31) == 0) { srk[w] = rk; spr[w] = pr; sv[w] = v; }
    __syncthreads();

    if (threadIdx.x == 0) {
        float R = 0.0f, P = 0.0f; int V = 0;
        int nw = blockDim.x >> 5;
        for (int k = 0; k < nw; k++) { R += srk[k]; P += spr[k]; V += sv[k]; }
        atomicAdd(&g_sum_rank, R);
        atomicAdd(&g_sum_per,  P);
        atomicAdd(&g_cnt,      V);
        __threadfence();
        unsigned d = atomicAdd(&g_done, 1u);
        if (d == (unsigned)(nblocks - 1)) {
            float sr = atomicAdd(&g_sum_rank, 0.0f);
            float sp2 = atomicAdd(&g_sum_per, 0.0f);
            int   cn = atomicAdd(&g_cnt, 0);
            float nv = fmaxf((float)cn, 1.0f);
            float lh = sr / nv;
            float lp = sp2 / nv;
            out[0] = lh + lp;
            out[1] = lh;
            out[2] = lp;
        }
    }
}

// ---------------- launch ----------------
// Inputs (metadata order): 0 preds_mat(f32), 1 preds_sub(f32), 2 inputs(f32 B*D),
// 3 targets_mat(int, B), 4 targets_sub(int, B), 5 user_answers(int, T*3)
extern "C" void kernel_launch(void* const* d_in, const int* in_sizes, int n_in,
                              void* d_out, int out_size) {
    const float* inputs = (const float*)d_in[2];
    const void*  tm     = d_in[3];
    const void*  ua     = d_in[5];
    int n_tm = in_sizes[3];
    int n_ua = in_sizes[5];
    int T = n_ua / 3;
    int D = in_sizes[2] / n_tm;

    k1_prep<<<1, 1024>>>(tm, ua, n_tm, n_ua);
    k2_dist<<<NUM_CLASSES * NUM_CLASSES, 128>>>(inputs, D);
    int nb = (T + 255) / 256;
    k3_main<<<nb, 256>>>(ua, T, nb, (float*)d_out);
}